// round 12
// baseline (speedup 1.0000x reference)
#include <cuda_runtime.h>
#include <cuda_fp16.h>
#include <cuda_bf16.h>
#include <math.h>
#include <stdint.h>

// Problem constants
#define B_SZ 2
#define S_LEN 2048
#define D_MODEL 1024
#define N_HEADS 16
#define DH 64
#define NTOK (B_SZ * S_LEN)          // 4096
#define WSZ (D_MODEL * D_MODEL)

// fp16 scratch
__device__ __half g_INh[3 * NTOK * D_MODEL];    // queries/keys/values fp16 (packed)
__device__ __half g_WTh[4 * WSZ];               // Wq^T..Wo^T fp16
__device__ __half g_QKVh[3 * NTOK * D_MODEL];   // projected Q,K,V fp16 (packed)
__device__ __half g_AOh[NTOK * D_MODEL];        // attention output fp16

// ===========================================================================
// PTX helpers (sm_80+ features only — valid under compute_103 virtual arch)
// ===========================================================================
__device__ __forceinline__ uint32_t smem_to_u32(const void* smem_ptr) {
    uint32_t addr;
    asm("{ .reg .u64 tmp; cvta.to.shared.u64 tmp, %1; cvt.u32.u64 %0, tmp; }"
        : "=r"(addr) : "l"(smem_ptr));
    return addr;
}

#define LDSM_X4(r0, r1, r2, r3, addr) \
    asm volatile("ldmatrix.sync.aligned.m8n8.x4.shared.b16 {%0,%1,%2,%3}, [%4];" \
        : "=r"(r0), "=r"(r1), "=r"(r2), "=r"(r3) : "r"(addr))

#define LDSM_X4_T(r0, r1, r2, r3, addr) \
    asm volatile("ldmatrix.sync.aligned.m8n8.x4.trans.shared.b16 {%0,%1,%2,%3}, [%4];" \
        : "=r"(r0), "=r"(r1), "=r"(r2), "=r"(r3) : "r"(addr))

#define MMA_F16(c0, c1, c2, c3, a0, a1, a2, a3, b0, b1) \
    asm volatile("mma.sync.aligned.m16n8k16.row.col.f32.f16.f16.f32 " \
        "{%0,%1,%2,%3}, {%4,%5,%6,%7}, {%8,%9}, {%0,%1,%2,%3};" \
        : "+f"(c0), "+f"(c1), "+f"(c2), "+f"(c3) \
        : "r"(a0), "r"(a1), "r"(a2), "r"(a3), "r"(b0), "r"(b1))

#define CP_ASYNC16(dst, src) \
    asm volatile("cp.async.cg.shared.global [%0], [%1], 16;" \
        :: "r"(dst), "l"(src) : "memory")
#define CP_COMMIT()  asm volatile("cp.async.commit_group;" ::: "memory")
#define CP_WAIT2()   asm volatile("cp.async.wait_group 2;" ::: "memory")
#define CP_WAIT1()   asm volatile("cp.async.wait_group 1;" ::: "memory")
#define CP_WAIT0()   asm volatile("cp.async.wait_group 0;" ::: "memory")

// SW128 swizzle for 128-byte rows
#define SWZ_MASK(rowByte) (((rowByte) >> 3) & 0x70)

// Packed softmax numerator for a score pair: p_i = exp(s_i/8), with the
// reference quirk (exact-zero score -> weight 0, i.e. masked to -1e30).
__device__ __forceinline__ uint32_t pexp2(float s0, float s1) {
    const float C = 0.18033688011111793f;   // log2(e)/8
    float x0 = s0 * C, x1 = s1 * C;
    uint32_t h, mask, e;
    asm("cvt.rn.f16x2.f32 %0, %1, %2;" : "=r"(h) : "f"(x1), "f"(x0));
    asm("set.ne.u32.f16x2 %0, %1, %2;" : "=r"(mask) : "r"(h), "r"(0u));
    asm("ex2.approx.f16x2 %0, %1;" : "=r"(e) : "r"(h));
    return e & mask;
}

#define ONES_H2 0x3C003C00u   // (1.0h, 1.0h) — B-fragment for row-sum MMA

// ===========================================================================
// Conversion kernels
// ===========================================================================
__global__ __launch_bounds__(256) void cvt_in_kernel(
    const float* __restrict__ q, const float* __restrict__ k,
    const float* __restrict__ v, __half* __restrict__ dst)
{
    const int z = blockIdx.z;
    const float* src = (z == 0) ? q : (z == 1) ? k : v;
    __half* d = dst + (size_t)z * NTOK * D_MODEL;
    const size_t i = ((size_t)blockIdx.x * 256 + threadIdx.x) * 8;
    float4 a = *(const float4*)(src + i);
    float4 b = *(const float4*)(src + i + 4);
    __half2 h[4];
    h[0] = __floats2half2_rn(a.x, a.y);
    h[1] = __floats2half2_rn(a.z, a.w);
    h[2] = __floats2half2_rn(b.x, b.y);
    h[3] = __floats2half2_rn(b.z, b.w);
    *(uint4*)(d + i) = *(uint4*)h;
}

// transpose + cvt: dst[n][k] = (half)src[k][n]
__global__ __launch_bounds__(256) void wtcvt_kernel(
    const float* __restrict__ w0, const float* __restrict__ w1,
    const float* __restrict__ w2, const float* __restrict__ w3,
    __half* __restrict__ dstBase)
{
    const int z = blockIdx.z;
    const float* src = (z == 0) ? w0 : (z == 1) ? w1 : (z == 2) ? w2 : w3;
    __half* dst = dstBase + (size_t)z * WSZ;
    __shared__ float t[32][33];
    const int bx = blockIdx.x * 32, by = blockIdx.y * 32;
    int x = bx + threadIdx.x;
    #pragma unroll
    for (int i = 0; i < 32; i += 8)
        t[threadIdx.y + i][threadIdx.x] = src[(size_t)(by + threadIdx.y + i) * D_MODEL + x];
    __syncthreads();
    x = by + threadIdx.x;
    #pragma unroll
    for (int i = 0; i < 32; i += 8)
        dst[(size_t)(bx + threadIdx.y + i) * D_MODEL + x] =
            __float2half_rn(t[threadIdx.x][threadIdx.y + i]);
}

// ===========================================================================
// fp16 HGEMM: C[M,1024] = A[M,1024] @ W with BT = W^T rows K-major (fp16).
// CTA tile 128x128, BK=64, 8 warps of 64x32, cp.async 3-stage ring,
// ONE __syncthreads per stage. blockIdx.z selects (A, B, C) via strides.
// Dyn smem 96KB: stage st at st*32768 (A 16K | B 16K).
// ===========================================================================
#define HG_SMEM 98304

template <bool HALF_OUT>
__global__ __launch_bounds__(256, 2) void hgemm_kernel(
    const __half* __restrict__ Abase, const __half* __restrict__ Bbase,
    void* __restrict__ Cbase, size_t aStride, size_t bStride, size_t cStride)
{
    extern __shared__ char smem[];
    const uint32_t smbase = smem_to_u32(smem);

    const __half* A = Abase + (size_t)blockIdx.z * aStride;
    const __half* B = Bbase + (size_t)blockIdx.z * bStride;

    const int tid  = threadIdx.x;
    const int wid  = tid >> 5;
    const int lane = tid & 31;
    const int rowBase = blockIdx.y * 128;
    const int colBase = blockIdx.x * 128;

    // loader: row lr, 64B half lh; 4x cp.async.16B each for A and B
    const int lr = tid >> 1;
    const int lh = tid & 1;
    const __half* Ag = A + (size_t)(rowBase + lr) * D_MODEL + lh * 32;
    const __half* Bg = B + (size_t)(colBase + lr) * D_MODEL + lh * 32;
    uint32_t stO[4];
    {
        const uint32_t rowByte = (uint32_t)lr * 128;
        const uint32_t msk = SWZ_MASK(rowByte);
        #pragma unroll
        for (int i = 0; i < 4; ++i)
            stO[i] = (rowByte + (uint32_t)lh * 64 + i * 16) ^ msk;
    }

    // fragment addressing
    const int warpRow = (wid >> 2) * 64;
    const int warpCol = (wid & 3) * 32;
    const int aRowL  = warpRow + ((lane >> 3) & 1) * 8 + (lane & 7);
    const int aKbyte = (lane >> 4) * 16;
    const int bRowL  = warpCol + (lane >> 4) * 8 + (lane & 7);
    const int bKbyte = ((lane >> 3) & 1) * 16;

    uint32_t aOff[4], aMsk[4];
    #pragma unroll
    for (int mt = 0; mt < 4; ++mt) {
        const uint32_t ro = (uint32_t)(aRowL + mt * 16) * 128;
        aOff[mt] = ro + aKbyte;
        aMsk[mt] = SWZ_MASK(ro);
    }
    uint32_t bOff[2], bMsk[2];
    #pragma unroll
    for (int j = 0; j < 2; ++j) {
        const uint32_t ro = (uint32_t)(bRowL + j * 16) * 128;
        bOff[j] = ro + bKbyte;
        bMsk[j] = SWZ_MASK(ro);
    }

    float acc[4][4][4];
    #pragma unroll
    for (int mt = 0; mt < 4; ++mt)
        #pragma unroll
        for (int nt = 0; nt < 4; ++nt)
            #pragma unroll
            for (int i = 0; i < 4; ++i) acc[mt][nt][i] = 0.f;

    // ---- prologue: stages 0 and 1 ----
    #pragma unroll
    for (int p = 0; p < 2; ++p) {
        const __half* ag = Ag + p * 64;
        const __half* bg = Bg + p * 64;
        const uint32_t base = smbase + p * 32768;
        #pragma unroll
        for (int i = 0; i < 4; ++i) CP_ASYNC16(base + stO[i], ag + i * 8);
        #pragma unroll
        for (int i = 0; i < 4; ++i) CP_ASYNC16(base + 16384 + stO[i], bg + i * 8);
        CP_COMMIT();
    }

    int st = 0;  // s % 3
    #pragma unroll 1
    for (int s = 0; s < 16; ++s) {
        if (s < 15) CP_WAIT1(); else CP_WAIT0();
        __syncthreads();
        if (s + 2 < 16) {
            const int st2 = (st + 2 >= 3) ? st - 1 : st + 2;
            const __half* ag = Ag + (s + 2) * 64;
            const __half* bg = Bg + (s + 2) * 64;
            const uint32_t base = smbase + st2 * 32768;
            #pragma unroll
            for (int i = 0; i < 4; ++i) CP_ASYNC16(base + stO[i], ag + i * 8);
            #pragma unroll
            for (int i = 0; i < 4; ++i) CP_ASYNC16(base + 16384 + stO[i], bg + i * 8);
            CP_COMMIT();
        }

        const uint32_t aST = smbase + st * 32768;
        const uint32_t bST = aST + 16384;
        st = (st == 2) ? 0 : st + 1;

        #pragma unroll
        for (int ks = 0; ks < 4; ++ks) {
            uint32_t af[4][4];
            #pragma unroll
            for (int mt = 0; mt < 4; ++mt)
                LDSM_X4(af[mt][0], af[mt][1], af[mt][2], af[mt][3],
                        aST + ((aOff[mt] + ks * 32) ^ aMsk[mt]));
            uint32_t bf[2][4];
            #pragma unroll
            for (int j = 0; j < 2; ++j)
                LDSM_X4(bf[j][0], bf[j][1], bf[j][2], bf[j][3],
                        bST + ((bOff[j] + ks * 32) ^ bMsk[j]));
            #pragma unroll
            for (int mt = 0; mt < 4; ++mt)
                #pragma unroll
                for (int nt = 0; nt < 4; ++nt) {
                    const int j = nt >> 1, hh = (nt & 1) * 2;
                    MMA_F16(acc[mt][nt][0], acc[mt][nt][1],
                            acc[mt][nt][2], acc[mt][nt][3],
                            af[mt][0], af[mt][1], af[mt][2], af[mt][3],
                            bf[j][hh], bf[j][hh + 1]);
                }
        }
    }

    // ---- epilogue ----
    const int erow = rowBase + warpRow + (lane >> 2);
    const int ecol = colBase + warpCol + (lane & 3) * 2;
    if (HALF_OUT) {
        __half* C = (__half*)Cbase + (size_t)blockIdx.z * cStride;
        #pragma unroll
        for (int mt = 0; mt < 4; ++mt)
            #pragma unroll
            for (int nt = 0; nt < 4; ++nt) {
                __half* p0 = C + (size_t)(erow + mt * 16) * D_MODEL + ecol + nt * 8;
                *(__half2*)p0 = __floats2half2_rn(acc[mt][nt][0], acc[mt][nt][1]);
                *(__half2*)(p0 + 8 * D_MODEL) =
                    __floats2half2_rn(acc[mt][nt][2], acc[mt][nt][3]);
            }
    } else {
        float* C = (float*)Cbase + (size_t)blockIdx.z * cStride;
        #pragma unroll
        for (int mt = 0; mt < 4; ++mt)
            #pragma unroll
            for (int nt = 0; nt < 4; ++nt) {
                float* p0 = C + (size_t)(erow + mt * 16) * D_MODEL + ecol + nt * 8;
                float2 v01; v01.x = acc[mt][nt][0]; v01.y = acc[mt][nt][1];
                float2 v23; v23.x = acc[mt][nt][2]; v23.y = acc[mt][nt][3];
                *(float2*)p0 = v01;
                *(float2*)(p0 + 8 * D_MODEL) = v23;
            }
    }
}

// ===========================================================================
// fp16 flash attention v3: transient-S (per-kv16-chunk S -> exp -> PV, no
// full S tile live), no-rescale softmax, f16x2 exponentials, ones-MMA row
// sums. 2-stage cp.async K/V ring (40KB smem) + launch_bounds(128, 5):
// 5 CTAs/SM (reg cap 102) for 20 warps/SM. Two syncthreads per kv tile
// (buffer reuse at depth 2). Grid (S/64, H, B), 128 threads.
// Smem: Q 8K | K ring 2x8K | V ring 2x8K = 40KB.
// ===========================================================================
#define AQ_OFF 0
#define AK_OFF 8192
#define AV_OFF 24576
#define A_SMEM 40960

__global__ __launch_bounds__(128, 5) void attn_f16_kernel(
    const __half* __restrict__ QKV, __half* __restrict__ AO)
{
    extern __shared__ char smem[];
    const uint32_t sb = smem_to_u32(smem);
    const int qt = blockIdx.x, h = blockIdx.y, b = blockIdx.z;
    const int tid = threadIdx.x, wid = tid >> 5, lane = tid & 31;

    const __half* Q = QKV;
    const __half* K = QKV + (size_t)NTOK * D_MODEL;
    const __half* V = QKV + 2 * (size_t)NTOK * D_MODEL;
    const size_t headBase = (size_t)(b * S_LEN) * D_MODEL + h * DH;

    // loader: row lr (0..63), 64B half lh
    const int lr = tid >> 1;
    const int lh = tid & 1;
    uint32_t stO[4];
    {
        const uint32_t rowByte = (uint32_t)lr * 128;
        const uint32_t msk = SWZ_MASK(rowByte);
        #pragma unroll
        for (int i = 0; i < 4; ++i)
            stO[i] = (rowByte + (uint32_t)lh * 64 + i * 16) ^ msk;
    }
    const __half* Kg = K + headBase + (size_t)lr * D_MODEL + lh * 32;
    const __half* Vg = V + headBase + (size_t)lr * D_MODEL + lh * 32;

    // ---- prologue: Q (group), KV0 (group), KV1 (group) ----
    {
        const __half* qg = Q + headBase + (size_t)(qt * 64 + lr) * D_MODEL + lh * 32;
        #pragma unroll
        for (int i = 0; i < 4; ++i) CP_ASYNC16(sb + AQ_OFF + stO[i], qg + i * 8);
        CP_COMMIT();
        #pragma unroll
        for (int p = 0; p < 2; ++p) {
            const __half* kg = Kg + (size_t)p * 64 * D_MODEL;
            const __half* vg = Vg + (size_t)p * 64 * D_MODEL;
            #pragma unroll
            for (int i = 0; i < 4; ++i) CP_ASYNC16(sb + AK_OFF + p * 8192 + stO[i], kg + i * 8);
            #pragma unroll
            for (int i = 0; i < 4; ++i) CP_ASYNC16(sb + AV_OFF + p * 8192 + stO[i], vg + i * 8);
            CP_COMMIT();
        }
        CP_WAIT2();        // Q complete
    }
    __syncthreads();

    // ---- fragment lane addressing ----
    const int aRowQ  = wid * 16 + ((lane >> 3) & 1) * 8 + (lane & 7);
    const int aKbyte = (lane >> 4) * 16;
    const uint32_t aRowByteQ = (uint32_t)aRowQ * 128;
    const uint32_t aMskQ = SWZ_MASK(aRowByteQ);

    const int bKbyte = ((lane >> 3) & 1) * 16;
    uint32_t bOff[4], bMsk[4];            // K (non-trans): rows = kv
    #pragma unroll
    for (int j2 = 0; j2 < 4; ++j2) {
        const uint32_t ro = (uint32_t)(j2 * 16 + (lane >> 4) * 8 + (lane & 7)) * 128;
        bOff[j2] = ro + bKbyte;
        bMsk[j2] = SWZ_MASK(ro);
    }
    // V (trans): rows = kv; k+8 via (lane>>3)&1, n+16B via lane>>4
    const uint32_t vRowByte = (uint32_t)(((lane >> 3) & 1) * 8 + (lane & 7)) * 128;
    const uint32_t vMsk = SWZ_MASK(vRowByte);
    const uint32_t vNb = (uint32_t)(lane >> 4) * 16;

    // Q fragments (register-resident for whole kernel)
    uint32_t qf[4][4];
    #pragma unroll
    for (int ks = 0; ks < 4; ++ks)
        LDSM_X4(qf[ks][0], qf[ks][1], qf[ks][2], qf[ks][3],
                sb + AQ_OFF + ((aRowByteQ + ks * 32 + aKbyte) ^ aMskQ));

    float racc[4];                  // ones-MMA accumulator: row sums of P
    racc[0] = racc[1] = racc[2] = racc[3] = 0.f;
    float o[8][4];
    #pragma unroll
    for (int nt = 0; nt < 8; ++nt)
        #pragma unroll
        for (int i = 0; i < 4; ++i) o[nt][i] = 0.f;

    const int t0 = lane & 3;
    const int rl = lane >> 2;

    #pragma unroll 1
    for (int jt = 0; jt < S_LEN / 64; ++jt) {
        if (jt < S_LEN / 64 - 1) CP_WAIT1(); else CP_WAIT0();
        __syncthreads();           // all threads' cp.async for buf jt&1 visible

        const uint32_t kST = sb + AK_OFF + (jt & 1) * 8192;
        const uint32_t vST = sb + AV_OFF + (jt & 1) * 8192;

        // ---- per kv16-chunk: S -> exp -> ones-MMA -> PV (transient S) ----
        #pragma unroll
        for (int c = 0; c < 4; ++c) {
            // S chunk [m16 x n16] over dh=64
            float s0[4], s1[4];
            #pragma unroll
            for (int i = 0; i < 4; ++i) { s0[i] = 0.f; s1[i] = 0.f; }
            #pragma unroll
            for (int ks = 0; ks < 4; ++ks) {
                uint32_t kf0, kf1, kf2, kf3;
                LDSM_X4(kf0, kf1, kf2, kf3,
                        kST + ((bOff[c] + ks * 32) ^ bMsk[c]));
                MMA_F16(s0[0], s0[1], s0[2], s0[3],
                        qf[ks][0], qf[ks][1], qf[ks][2], qf[ks][3], kf0, kf1);
                MMA_F16(s1[0], s1[1], s1[2], s1[3],
                        qf[ks][0], qf[ks][1], qf[ks][2], qf[ks][3], kf2, kf3);
            }

            // exp(score/8) with exact-zero quirk; result is the PV A-fragment
            uint32_t pa0 = pexp2(s0[0], s0[1]);
            uint32_t pa1 = pexp2(s0[2], s0[3]);
            uint32_t pa2 = pexp2(s1[0], s1[1]);
            uint32_t pa3 = pexp2(s1[2], s1[3]);

            // row sums via ones-column MMA
            MMA_F16(racc[0], racc[1], racc[2], racc[3],
                    pa0, pa1, pa2, pa3, ONES_H2, ONES_H2);

            // O += P_chunk @ V[kv chunk c, :]
            #pragma unroll
            for (int jn = 0; jn < 4; ++jn) {
                uint32_t vf0, vf1, vf2, vf3;
                LDSM_X4_T(vf0, vf1, vf2, vf3,
                          vST + (uint32_t)c * 2048 +
                          ((vRowByte + jn * 32 + vNb) ^ vMsk));
                MMA_F16(o[2 * jn][0], o[2 * jn][1], o[2 * jn][2], o[2 * jn][3],
                        pa0, pa1, pa2, pa3, vf0, vf1);
                MMA_F16(o[2 * jn + 1][0], o[2 * jn + 1][1],
                        o[2 * jn + 1][2], o[2 * jn + 1][3],
                        pa0, pa1, pa2, pa3, vf2, vf3);
            }
        }

        __syncthreads();           // all reads of buf jt&1 done before refill
        if (jt + 2 < S_LEN / 64) {
            const __half* kg = Kg + (size_t)(jt + 2) * 64 * D_MODEL;
            const __half* vg = Vg + (size_t)(jt + 2) * 64 * D_MODEL;
            const uint32_t nb = (uint32_t)(jt & 1);   // (jt+2)&1 == jt&1
            #pragma unroll
            for (int i = 0; i < 4; ++i) CP_ASYNC16(sb + AK_OFF + nb * 8192 + stO[i], kg + i * 8);
            #pragma unroll
            for (int i = 0; i < 4; ++i) CP_ASYNC16(sb + AV_OFF + nb * 8192 + stO[i], vg + i * 8);
            CP_COMMIT();
        }
    }

    // ---- epilogue: row sums already reduced by the ones-MMA ----
    const float inv0 = 1.f / racc[0], inv1 = 1.f / racc[2];

    const int row0 = qt * 64 + wid * 16 + rl;
    __half* ob0 = AO + headBase + (size_t)row0 * D_MODEL;
    __half* ob1 = AO + headBase + (size_t)(row0 + 8) * D_MODEL;
    #pragma unroll
    for (int nt = 0; nt < 8; ++nt) {
        const int col = nt * 8 + 2 * t0;
        *(__half2*)(ob0 + col) = __floats2half2_rn(o[nt][0] * inv0, o[nt][1] * inv0);
        *(__half2*)(ob1 + col) = __floats2half2_rn(o[nt][2] * inv1, o[nt][3] * inv1);
    }
}

// ---------------------------------------------------------------------------
extern "C" void kernel_launch(void* const* d_in, const int* in_sizes, int n_in,
                              void* d_out, int out_size)
{
    const float* queries = (const float*)d_in[0];
    const float* keys    = (const float*)d_in[1];
    const float* values  = (const float*)d_in[2];
    const float* Wq      = (const float*)d_in[3];
    const float* Wk      = (const float*)d_in[4];
    const float* Wv      = (const float*)d_in[5];
    const float* Wo      = (const float*)d_in[6];
    float* out = (float*)d_out;

    __half *pINh, *pWTh, *pQKVh, *pAOh;
    cudaGetSymbolAddress((void**)&pINh,  g_INh);
    cudaGetSymbolAddress((void**)&pWTh,  g_WTh);
    cudaGetSymbolAddress((void**)&pQKVh, g_QKVh);
    cudaGetSymbolAddress((void**)&pAOh,  g_AOh);

    // 1) convert inputs to fp16 (packed) and weights to transposed fp16
    dim3 cg(NTOK * D_MODEL / (256 * 8), 1, 3);
    cvt_in_kernel<<<cg, 256>>>(queries, keys, values, pINh);
    dim3 wg(D_MODEL / 32, D_MODEL / 32, 4), wb(32, 8);
    wtcvt_kernel<<<wg, wb>>>(Wq, Wk, Wv, Wo, pWTh);

    // 2) fused Q/K/V projections: one launch, z = 0..2
    cudaFuncSetAttribute(hgemm_kernel<true>,
                         cudaFuncAttributeMaxDynamicSharedMemorySize, HG_SMEM);
    cudaFuncSetAttribute(hgemm_kernel<false>,
                         cudaFuncAttributeMaxDynamicSharedMemorySize, HG_SMEM);
    dim3 gg(D_MODEL / 128, NTOK / 128, 3);   // (8, 32, 3)
    hgemm_kernel<true><<<gg, 256, HG_SMEM>>>(
        pINh, pWTh, pQKVh,
        (size_t)NTOK * D_MODEL, (size_t)WSZ, (size_t)NTOK * D_MODEL);

    // 3) attention
    cudaFuncSetAttribute(attn_f16_kernel,
                         cudaFuncAttributeMaxDynamicSharedMemorySize, A_SMEM);
    dim3 ag(S_LEN / 64, N_HEADS, B_SZ);
    attn_f16_kernel<<<ag, 128, A_SMEM>>>(pQKVh, pAOh);

    // 4) output projection (fp32 out)
    dim3 og(D_MODEL / 128, NTOK / 128, 1);
    hgemm_kernel<false><<<og, 256, HG_SMEM>>>(
        pAOh, pWTh + 3 * (size_t)WSZ, out, 0, 0, 0);
}

// round 13
// speedup vs baseline: 1.0614x; 1.0614x over previous
#include <cuda_runtime.h>
#include <cuda_fp16.h>
#include <cuda_bf16.h>
#include <math.h>
#include <stdint.h>

// Problem constants
#define B_SZ 2
#define S_LEN 2048
#define D_MODEL 1024
#define N_HEADS 16
#define DH 64
#define NTOK (B_SZ * S_LEN)          // 4096
#define WSZ (D_MODEL * D_MODEL)

// fp16 scratch
__device__ __half g_INh[3 * NTOK * D_MODEL];    // queries/keys/values fp16 (packed)
__device__ __half g_WTh[4 * WSZ];               // Wq^T..Wo^T fp16
__device__ __half g_QKVh[3 * NTOK * D_MODEL];   // projected Q,K,V fp16 (packed)
__device__ __half g_AOh[NTOK * D_MODEL];        // attention output fp16

// ===========================================================================
// PTX helpers (sm_80+ features only — valid under compute_103 virtual arch)
// ===========================================================================
__device__ __forceinline__ uint32_t smem_to_u32(const void* smem_ptr) {
    uint32_t addr;
    asm("{ .reg .u64 tmp; cvta.to.shared.u64 tmp, %1; cvt.u32.u64 %0, tmp; }"
        : "=r"(addr) : "l"(smem_ptr));
    return addr;
}

#define LDSM_X4(r0, r1, r2, r3, addr) \
    asm volatile("ldmatrix.sync.aligned.m8n8.x4.shared.b16 {%0,%1,%2,%3}, [%4];" \
        : "=r"(r0), "=r"(r1), "=r"(r2), "=r"(r3) : "r"(addr))

#define LDSM_X4_T(r0, r1, r2, r3, addr) \
    asm volatile("ldmatrix.sync.aligned.m8n8.x4.trans.shared.b16 {%0,%1,%2,%3}, [%4];" \
        : "=r"(r0), "=r"(r1), "=r"(r2), "=r"(r3) : "r"(addr))

#define MMA_F16(c0, c1, c2, c3, a0, a1, a2, a3, b0, b1) \
    asm volatile("mma.sync.aligned.m16n8k16.row.col.f32.f16.f16.f32 " \
        "{%0,%1,%2,%3}, {%4,%5,%6,%7}, {%8,%9}, {%0,%1,%2,%3};" \
        : "+f"(c0), "+f"(c1), "+f"(c2), "+f"(c3) \
        : "r"(a0), "r"(a1), "r"(a2), "r"(a3), "r"(b0), "r"(b1))

#define CP_ASYNC16(dst, src) \
    asm volatile("cp.async.cg.shared.global [%0], [%1], 16;" \
        :: "r"(dst), "l"(src) : "memory")
#define CP_COMMIT()  asm volatile("cp.async.commit_group;" ::: "memory")
#define CP_WAIT2()   asm volatile("cp.async.wait_group 2;" ::: "memory")
#define CP_WAIT1()   asm volatile("cp.async.wait_group 1;" ::: "memory")
#define CP_WAIT0()   asm volatile("cp.async.wait_group 0;" ::: "memory")

// SW128 swizzle for 128-byte rows
#define SWZ_MASK(rowByte) (((rowByte) >> 3) & 0x70)

// Packed softmax numerator for a score pair: p_i = exp(s_i/8), with the
// reference quirk (exact-zero score -> weight 0, i.e. masked to -1e30).
__device__ __forceinline__ uint32_t pexp2(float s0, float s1) {
    const float C = 0.18033688011111793f;   // log2(e)/8
    float x0 = s0 * C, x1 = s1 * C;
    uint32_t h, mask, e;
    asm("cvt.rn.f16x2.f32 %0, %1, %2;" : "=r"(h) : "f"(x1), "f"(x0));
    asm("set.ne.u32.f16x2 %0, %1, %2;" : "=r"(mask) : "r"(h), "r"(0u));
    asm("ex2.approx.f16x2 %0, %1;" : "=r"(e) : "r"(h));
    return e & mask;
}

#define ONES_H2 0x3C003C00u   // (1.0h, 1.0h) — B-fragment for row-sum MMA

// ===========================================================================
// Conversion kernels
// ===========================================================================
__global__ __launch_bounds__(256) void cvt_in_kernel(
    const float* __restrict__ q, const float* __restrict__ k,
    const float* __restrict__ v, __half* __restrict__ dst)
{
    const int z = blockIdx.z;
    const float* src = (z == 0) ? q : (z == 1) ? k : v;
    __half* d = dst + (size_t)z * NTOK * D_MODEL;
    const size_t i = ((size_t)blockIdx.x * 256 + threadIdx.x) * 8;
    float4 a = *(const float4*)(src + i);
    float4 b = *(const float4*)(src + i + 4);
    __half2 h[4];
    h[0] = __floats2half2_rn(a.x, a.y);
    h[1] = __floats2half2_rn(a.z, a.w);
    h[2] = __floats2half2_rn(b.x, b.y);
    h[3] = __floats2half2_rn(b.z, b.w);
    *(uint4*)(d + i) = *(uint4*)h;
}

// transpose + cvt: dst[n][k] = (half)src[k][n]
__global__ __launch_bounds__(256) void wtcvt_kernel(
    const float* __restrict__ w0, const float* __restrict__ w1,
    const float* __restrict__ w2, const float* __restrict__ w3,
    __half* __restrict__ dstBase)
{
    const int z = blockIdx.z;
    const float* src = (z == 0) ? w0 : (z == 1) ? w1 : (z == 2) ? w2 : w3;
    __half* dst = dstBase + (size_t)z * WSZ;
    __shared__ float t[32][33];
    const int bx = blockIdx.x * 32, by = blockIdx.y * 32;
    int x = bx + threadIdx.x;
    #pragma unroll
    for (int i = 0; i < 32; i += 8)
        t[threadIdx.y + i][threadIdx.x] = src[(size_t)(by + threadIdx.y + i) * D_MODEL + x];
    __syncthreads();
    x = by + threadIdx.x;
    #pragma unroll
    for (int i = 0; i < 32; i += 8)
        dst[(size_t)(bx + threadIdx.y + i) * D_MODEL + x] =
            __float2half_rn(t[threadIdx.x][threadIdx.y + i]);
}

// ===========================================================================
// fp16 HGEMM: C[M,1024] = A[M,1024] @ W with BT = W^T rows K-major (fp16).
// CTA tile 128x128, BK=64, 8 warps of 64x32, cp.async 3-stage ring,
// ONE __syncthreads per stage. blockIdx.z selects (A, B, C) via strides.
// Dyn smem 96KB: stage st at st*32768 (A 16K | B 16K).  (unchanged)
// ===========================================================================
#define HG_SMEM 98304

template <bool HALF_OUT>
__global__ __launch_bounds__(256, 2) void hgemm_kernel(
    const __half* __restrict__ Abase, const __half* __restrict__ Bbase,
    void* __restrict__ Cbase, size_t aStride, size_t bStride, size_t cStride)
{
    extern __shared__ char smem[];
    const uint32_t smbase = smem_to_u32(smem);

    const __half* A = Abase + (size_t)blockIdx.z * aStride;
    const __half* B = Bbase + (size_t)blockIdx.z * bStride;

    const int tid  = threadIdx.x;
    const int wid  = tid >> 5;
    const int lane = tid & 31;
    const int rowBase = blockIdx.y * 128;
    const int colBase = blockIdx.x * 128;

    const int lr = tid >> 1;
    const int lh = tid & 1;
    const __half* Ag = A + (size_t)(rowBase + lr) * D_MODEL + lh * 32;
    const __half* Bg = B + (size_t)(colBase + lr) * D_MODEL + lh * 32;
    uint32_t stO[4];
    {
        const uint32_t rowByte = (uint32_t)lr * 128;
        const uint32_t msk = SWZ_MASK(rowByte);
        #pragma unroll
        for (int i = 0; i < 4; ++i)
            stO[i] = (rowByte + (uint32_t)lh * 64 + i * 16) ^ msk;
    }

    const int warpRow = (wid >> 2) * 64;
    const int warpCol = (wid & 3) * 32;
    const int aRowL  = warpRow + ((lane >> 3) & 1) * 8 + (lane & 7);
    const int aKbyte = (lane >> 4) * 16;
    const int bRowL  = warpCol + (lane >> 4) * 8 + (lane & 7);
    const int bKbyte = ((lane >> 3) & 1) * 16;

    uint32_t aOff[4], aMsk[4];
    #pragma unroll
    for (int mt = 0; mt < 4; ++mt) {
        const uint32_t ro = (uint32_t)(aRowL + mt * 16) * 128;
        aOff[mt] = ro + aKbyte;
        aMsk[mt] = SWZ_MASK(ro);
    }
    uint32_t bOff[2], bMsk[2];
    #pragma unroll
    for (int j = 0; j < 2; ++j) {
        const uint32_t ro = (uint32_t)(bRowL + j * 16) * 128;
        bOff[j] = ro + bKbyte;
        bMsk[j] = SWZ_MASK(ro);
    }

    float acc[4][4][4];
    #pragma unroll
    for (int mt = 0; mt < 4; ++mt)
        #pragma unroll
        for (int nt = 0; nt < 4; ++nt)
            #pragma unroll
            for (int i = 0; i < 4; ++i) acc[mt][nt][i] = 0.f;

    #pragma unroll
    for (int p = 0; p < 2; ++p) {
        const __half* ag = Ag + p * 64;
        const __half* bg = Bg + p * 64;
        const uint32_t base = smbase + p * 32768;
        #pragma unroll
        for (int i = 0; i < 4; ++i) CP_ASYNC16(base + stO[i], ag + i * 8);
        #pragma unroll
        for (int i = 0; i < 4; ++i) CP_ASYNC16(base + 16384 + stO[i], bg + i * 8);
        CP_COMMIT();
    }

    int st = 0;  // s % 3
    #pragma unroll 1
    for (int s = 0; s < 16; ++s) {
        if (s < 15) CP_WAIT1(); else CP_WAIT0();
        __syncthreads();
        if (s + 2 < 16) {
            const int st2 = (st + 2 >= 3) ? st - 1 : st + 2;
            const __half* ag = Ag + (s + 2) * 64;
            const __half* bg = Bg + (s + 2) * 64;
            const uint32_t base = smbase + st2 * 32768;
            #pragma unroll
            for (int i = 0; i < 4; ++i) CP_ASYNC16(base + stO[i], ag + i * 8);
            #pragma unroll
            for (int i = 0; i < 4; ++i) CP_ASYNC16(base + 16384 + stO[i], bg + i * 8);
            CP_COMMIT();
        }

        const uint32_t aST = smbase + st * 32768;
        const uint32_t bST = aST + 16384;
        st = (st == 2) ? 0 : st + 1;

        #pragma unroll
        for (int ks = 0; ks < 4; ++ks) {
            uint32_t af[4][4];
            #pragma unroll
            for (int mt = 0; mt < 4; ++mt)
                LDSM_X4(af[mt][0], af[mt][1], af[mt][2], af[mt][3],
                        aST + ((aOff[mt] + ks * 32) ^ aMsk[mt]));
            uint32_t bf[2][4];
            #pragma unroll
            for (int j = 0; j < 2; ++j)
                LDSM_X4(bf[j][0], bf[j][1], bf[j][2], bf[j][3],
                        bST + ((bOff[j] + ks * 32) ^ bMsk[j]));
            #pragma unroll
            for (int mt = 0; mt < 4; ++mt)
                #pragma unroll
                for (int nt = 0; nt < 4; ++nt) {
                    const int j = nt >> 1, hh = (nt & 1) * 2;
                    MMA_F16(acc[mt][nt][0], acc[mt][nt][1],
                            acc[mt][nt][2], acc[mt][nt][3],
                            af[mt][0], af[mt][1], af[mt][2], af[mt][3],
                            bf[j][hh], bf[j][hh + 1]);
                }
        }
    }

    const int erow = rowBase + warpRow + (lane >> 2);
    const int ecol = colBase + warpCol + (lane & 3) * 2;
    if (HALF_OUT) {
        __half* C = (__half*)Cbase + (size_t)blockIdx.z * cStride;
        #pragma unroll
        for (int mt = 0; mt < 4; ++mt)
            #pragma unroll
            for (int nt = 0; nt < 4; ++nt) {
                __half* p0 = C + (size_t)(erow + mt * 16) * D_MODEL + ecol + nt * 8;
                *(__half2*)p0 = __floats2half2_rn(acc[mt][nt][0], acc[mt][nt][1]);
                *(__half2*)(p0 + 8 * D_MODEL) =
                    __floats2half2_rn(acc[mt][nt][2], acc[mt][nt][3]);
            }
    } else {
        float* C = (float*)Cbase + (size_t)blockIdx.z * cStride;
        #pragma unroll
        for (int mt = 0; mt < 4; ++mt)
            #pragma unroll
            for (int nt = 0; nt < 4; ++nt) {
                float* p0 = C + (size_t)(erow + mt * 16) * D_MODEL + ecol + nt * 8;
                float2 v01; v01.x = acc[mt][nt][0]; v01.y = acc[mt][nt][1];
                float2 v23; v23.x = acc[mt][nt][2]; v23.y = acc[mt][nt][3];
                *(float2*)p0 = v01;
                *(float2*)(p0 + 8 * D_MODEL) = v23;
            }
    }
}

// ===========================================================================
// fp16 flash attention v4: m32 warp tiles — each warp owns 32 q-rows, so
// every K/V fragment load feeds 2x the MMAs (halves smem-port bytes/FLOP,
// the measured co-limiter). CTA = 4 warps = 128 q-rows. Full-S per tile,
// no-rescale softmax, f16x2 exp, ones-MMA row sums, P direct from regs.
// 3-stage cp.async K/V ring, ONE sync per kv tile. 2 CTAs/SM.
// Grid (S/128, H, B), 128 threads.
// Smem: Q 16K | K ring 3x8K | V ring 3x8K = 64KB.
// ===========================================================================
#define AQ_OFF 0
#define AK_OFF 16384
#define AV_OFF 40960
#define A_SMEM 65536

__global__ __launch_bounds__(128, 2) void attn_f16_kernel(
    const __half* __restrict__ QKV, __half* __restrict__ AO)
{
    extern __shared__ char smem[];
    const uint32_t sb = smem_to_u32(smem);
    const int qt = blockIdx.x, h = blockIdx.y, b = blockIdx.z;
    const int tid = threadIdx.x, wid = tid >> 5, lane = tid & 31;

    const __half* Q = QKV;
    const __half* K = QKV + (size_t)NTOK * D_MODEL;
    const __half* V = QKV + 2 * (size_t)NTOK * D_MODEL;
    const size_t headBase = (size_t)(b * S_LEN) * D_MODEL + h * DH;

    // K/V loader: row lr (0..63), 64B half lh
    const int lr = tid >> 1;
    const int lh = tid & 1;
    uint32_t stO[4];
    {
        const uint32_t rowByte = (uint32_t)lr * 128;
        const uint32_t msk = SWZ_MASK(rowByte);
        #pragma unroll
        for (int i = 0; i < 4; ++i)
            stO[i] = (rowByte + (uint32_t)lh * 64 + i * 16) ^ msk;
    }
    const __half* Kg = K + headBase + (size_t)lr * D_MODEL + lh * 32;
    const __half* Vg = V + headBase + (size_t)lr * D_MODEL + lh * 32;

    // ---- prologue: Q tile (128 rows, 1 row/thread), KV0, KV1 ----
    {
        const __half* qg = Q + headBase + (size_t)(qt * 128 + tid) * D_MODEL;
        const uint32_t qRowByte = (uint32_t)tid * 128;
        const uint32_t qMsk = SWZ_MASK(qRowByte);
        #pragma unroll
        for (int j = 0; j < 8; ++j)
            CP_ASYNC16(sb + AQ_OFF + ((qRowByte + j * 16) ^ qMsk), qg + j * 8);
        CP_COMMIT();
        #pragma unroll
        for (int p = 0; p < 2; ++p) {
            const __half* kg = Kg + (size_t)p * 64 * D_MODEL;
            const __half* vg = Vg + (size_t)p * 64 * D_MODEL;
            #pragma unroll
            for (int i = 0; i < 4; ++i) CP_ASYNC16(sb + AK_OFF + p * 8192 + stO[i], kg + i * 8);
            #pragma unroll
            for (int i = 0; i < 4; ++i) CP_ASYNC16(sb + AV_OFF + p * 8192 + stO[i], vg + i * 8);
            CP_COMMIT();
        }
        CP_WAIT2();        // Q complete
    }
    __syncthreads();

    // ---- fragment lane addressing ----
    const int aKbyte = (lane >> 4) * 16;
    uint32_t aRowByteQ[2], aMskQ[2];
    #pragma unroll
    for (int mh = 0; mh < 2; ++mh) {
        const int r = wid * 32 + mh * 16 + ((lane >> 3) & 1) * 8 + (lane & 7);
        aRowByteQ[mh] = (uint32_t)r * 128;
        aMskQ[mh] = SWZ_MASK(aRowByteQ[mh]);
    }

    const int bKbyte = ((lane >> 3) & 1) * 16;
    uint32_t bOff[4], bMsk[4];            // K (non-trans): rows = kv
    #pragma unroll
    for (int j2 = 0; j2 < 4; ++j2) {
        const uint32_t ro = (uint32_t)(j2 * 16 + (lane >> 4) * 8 + (lane & 7)) * 128;
        bOff[j2] = ro + bKbyte;
        bMsk[j2] = SWZ_MASK(ro);
    }
    // V (trans): rows = kv; k+8 via (lane>>3)&1, n+16B via lane>>4
    const uint32_t vRowByte = (uint32_t)(((lane >> 3) & 1) * 8 + (lane & 7)) * 128;
    const uint32_t vMsk = SWZ_MASK(vRowByte);
    const uint32_t vNb = (uint32_t)(lane >> 4) * 16;

    // Q fragments: both m16 halves, register-resident for whole kernel
    uint32_t qf[2][4][4];
    #pragma unroll
    for (int mh = 0; mh < 2; ++mh)
        #pragma unroll
        for (int ks = 0; ks < 4; ++ks)
            LDSM_X4(qf[mh][ks][0], qf[mh][ks][1], qf[mh][ks][2], qf[mh][ks][3],
                    sb + AQ_OFF + ((aRowByteQ[mh] + ks * 32 + aKbyte) ^ aMskQ[mh]));

    float racc[2][4];               // ones-MMA row sums per m-half
    #pragma unroll
    for (int mh = 0; mh < 2; ++mh)
        racc[mh][0] = racc[mh][1] = racc[mh][2] = racc[mh][3] = 0.f;
    float o[2][8][4];
    #pragma unroll
    for (int mh = 0; mh < 2; ++mh)
        #pragma unroll
        for (int nt = 0; nt < 8; ++nt)
            #pragma unroll
            for (int i = 0; i < 4; ++i) o[mh][nt][i] = 0.f;

    const int t0 = lane & 3;
    const int rl = lane >> 2;

    int st = 0;   // jt % 3
    #pragma unroll 1
    for (int jt = 0; jt < S_LEN / 64; ++jt) {
        if (jt < S_LEN / 64 - 1) CP_WAIT1(); else CP_WAIT0();
        __syncthreads();
        if (jt + 2 < S_LEN / 64) {
            const int st2 = (st + 2 >= 3) ? st - 1 : st + 2;
            const __half* kg = Kg + (size_t)(jt + 2) * 64 * D_MODEL;
            const __half* vg = Vg + (size_t)(jt + 2) * 64 * D_MODEL;
            #pragma unroll
            for (int i = 0; i < 4; ++i) CP_ASYNC16(sb + AK_OFF + st2 * 8192 + stO[i], kg + i * 8);
            #pragma unroll
            for (int i = 0; i < 4; ++i) CP_ASYNC16(sb + AV_OFF + st2 * 8192 + stO[i], vg + i * 8);
            CP_COMMIT();
        }

        const uint32_t kST = sb + AK_OFF + st * 8192;
        const uint32_t vST = sb + AV_OFF + st * 8192;
        st = (st == 2) ? 0 : st + 1;

        // ---- S = Q K^T for BOTH m-halves (each K frag feeds 4 MMAs) ----
        float s[2][8][4];
        #pragma unroll
        for (int mh = 0; mh < 2; ++mh)
            #pragma unroll
            for (int nt = 0; nt < 8; ++nt)
                #pragma unroll
                for (int i = 0; i < 4; ++i) s[mh][nt][i] = 0.f;
        #pragma unroll
        for (int ks = 0; ks < 4; ++ks) {
            #pragma unroll
            for (int j2 = 0; j2 < 4; ++j2) {
                uint32_t kf0, kf1, kf2, kf3;
                LDSM_X4(kf0, kf1, kf2, kf3,
                        kST + ((bOff[j2] + ks * 32) ^ bMsk[j2]));
                #pragma unroll
                for (int mh = 0; mh < 2; ++mh) {
                    MMA_F16(s[mh][2 * j2][0], s[mh][2 * j2][1],
                            s[mh][2 * j2][2], s[mh][2 * j2][3],
                            qf[mh][ks][0], qf[mh][ks][1], qf[mh][ks][2], qf[mh][ks][3],
                            kf0, kf1);
                    MMA_F16(s[mh][2 * j2 + 1][0], s[mh][2 * j2 + 1][1],
                            s[mh][2 * j2 + 1][2], s[mh][2 * j2 + 1][3],
                            qf[mh][ks][0], qf[mh][ks][1], qf[mh][ks][2], qf[mh][ks][3],
                            kf2, kf3);
                }
            }
        }

        // ---- exp (quirk included); result = PV A-fragments ----
        uint32_t pa[2][8][2];
        #pragma unroll
        for (int mh = 0; mh < 2; ++mh)
            #pragma unroll
            for (int nt = 0; nt < 8; ++nt) {
                pa[mh][nt][0] = pexp2(s[mh][nt][0], s[mh][nt][1]);
                pa[mh][nt][1] = pexp2(s[mh][nt][2], s[mh][nt][3]);
            }

        // ---- O += P @ V (each V frag feeds 4 MMAs) + ones-MMA row sums ----
        #pragma unroll
        for (int pk = 0; pk < 4; ++pk) {
            #pragma unroll
            for (int mh = 0; mh < 2; ++mh)
                MMA_F16(racc[mh][0], racc[mh][1], racc[mh][2], racc[mh][3],
                        pa[mh][2 * pk][0], pa[mh][2 * pk][1],
                        pa[mh][2 * pk + 1][0], pa[mh][2 * pk + 1][1],
                        ONES_H2, ONES_H2);
            #pragma unroll
            for (int jn = 0; jn < 4; ++jn) {
                uint32_t vf0, vf1, vf2, vf3;
                LDSM_X4_T(vf0, vf1, vf2, vf3,
                          vST + (uint32_t)pk * 2048 +
                          ((vRowByte + jn * 32 + vNb) ^ vMsk));
                #pragma unroll
                for (int mh = 0; mh < 2; ++mh) {
                    MMA_F16(o[mh][2 * jn][0], o[mh][2 * jn][1],
                            o[mh][2 * jn][2], o[mh][2 * jn][3],
                            pa[mh][2 * pk][0], pa[mh][2 * pk][1],
                            pa[mh][2 * pk + 1][0], pa[mh][2 * pk + 1][1],
                            vf0, vf1);
                    MMA_F16(o[mh][2 * jn + 1][0], o[mh][2 * jn + 1][1],
                            o[mh][2 * jn + 1][2], o[mh][2 * jn + 1][3],
                            pa[mh][2 * pk][0], pa[mh][2 * pk][1],
                            pa[mh][2 * pk + 1][0], pa[mh][2 * pk + 1][1],
                            vf2, vf3);
                }
            }
        }
    }

    // ---- epilogue: row sums already reduced by the ones-MMA ----
    #pragma unroll
    for (int mh = 0; mh < 2; ++mh) {
        const float inv0 = 1.f / racc[mh][0], inv1 = 1.f / racc[mh][2];
        const int row0 = qt * 128 + wid * 32 + mh * 16 + rl;
        __half* ob0 = AO + headBase + (size_t)row0 * D_MODEL;
        __half* ob1 = AO + headBase + (size_t)(row0 + 8) * D_MODEL;
        #pragma unroll
        for (int nt = 0; nt < 8; ++nt) {
            const int col = nt * 8 + 2 * t0;
            *(__half2*)(ob0 + col) =
                __floats2half2_rn(o[mh][nt][0] * inv0, o[mh][nt][1] * inv0);
            *(__half2*)(ob1 + col) =
                __floats2half2_rn(o[mh][nt][2] * inv1, o[mh][nt][3] * inv1);
        }
    }
}

// ---------------------------------------------------------------------------
extern "C" void kernel_launch(void* const* d_in, const int* in_sizes, int n_in,
                              void* d_out, int out_size)
{
    const float* queries = (const float*)d_in[0];
    const float* keys    = (const float*)d_in[1];
    const float* values  = (const float*)d_in[2];
    const float* Wq      = (const float*)d_in[3];
    const float* Wk      = (const float*)d_in[4];
    const float* Wv      = (const float*)d_in[5];
    const float* Wo      = (const float*)d_in[6];
    float* out = (float*)d_out;

    __half *pINh, *pWTh, *pQKVh, *pAOh;
    cudaGetSymbolAddress((void**)&pINh,  g_INh);
    cudaGetSymbolAddress((void**)&pWTh,  g_WTh);
    cudaGetSymbolAddress((void**)&pQKVh, g_QKVh);
    cudaGetSymbolAddress((void**)&pAOh,  g_AOh);

    // 1) convert inputs to fp16 (packed) and weights to transposed fp16
    dim3 cg(NTOK * D_MODEL / (256 * 8), 1, 3);
    cvt_in_kernel<<<cg, 256>>>(queries, keys, values, pINh);
    dim3 wg(D_MODEL / 32, D_MODEL / 32, 4), wb(32, 8);
    wtcvt_kernel<<<wg, wb>>>(Wq, Wk, Wv, Wo, pWTh);

    // 2) fused Q/K/V projections: one launch, z = 0..2
    cudaFuncSetAttribute(hgemm_kernel<true>,
                         cudaFuncAttributeMaxDynamicSharedMemorySize, HG_SMEM);
    cudaFuncSetAttribute(hgemm_kernel<false>,
                         cudaFuncAttributeMaxDynamicSharedMemorySize, HG_SMEM);
    dim3 gg(D_MODEL / 128, NTOK / 128, 3);   // (8, 32, 3)
    hgemm_kernel<true><<<gg, 256, HG_SMEM>>>(
        pINh, pWTh, pQKVh,
        (size_t)NTOK * D_MODEL, (size_t)WSZ, (size_t)NTOK * D_MODEL);

    // 3) attention (m32 warps: 128 q-rows per CTA)
    cudaFuncSetAttribute(attn_f16_kernel,
                         cudaFuncAttributeMaxDynamicSharedMemorySize, A_SMEM);
    dim3 ag(S_LEN / 128, N_HEADS, B_SZ);   // (16, 16, 2)
    attn_f16_kernel<<<ag, 128, A_SMEM>>>(pQKVh, pAOh);

    // 4) output projection (fp32 out)
    dim3 og(D_MODEL / 128, NTOK / 128, 1);
    hgemm_kernel<false><<<og, 256, HG_SMEM>>>(
        pAOh, pWTh + 3 * (size_t)WSZ, out, 0, 0, 0);
}